// round 2
// baseline (speedup 1.0000x reference)
#include <cuda_runtime.h>
#include <cstdint>

// ============================================================================
// LSTM cell on base sm_103 ISA (no tcgen05/TMA available in this toolchain):
// tf32 mma.sync m16n8k8 GEMM with cp.async 4-stage pipeline, fused gate
// epilogue via gate-interleaved weight packing.
//
// z[M=4096, N=8192] = A[4096, 4096] @ B[4096, 8192]
//   A = [x | h] (K-concat), B[k][4u+g] = W{x,h}{f,i,o,g}[k][u]  (gate-interleaved)
// Inputs: 0:x 1:h 2:c 3:Wxf 4:Wxi 5:Wxo 6:Wxg 7:bf 8:bi 9:bo 10:bg
//         11:Whf 12:Whi 13:Who 14:Whg
// ============================================================================

#define MTOT 4096
#define KTOT 4096
#define NTOT 8192
#define UDIM 2048

#define TM 256
#define TN 128
#define TK 16
#define STAGES 4
#define ALD 20    // floats per A smem row (16 + pad for conflict-free frags)
#define BLD 136   // floats per B smem row (128 + pad)
#define ZLD 132   // floats per z smem row in epilogue

#define SA_BYTES (TM * ALD * 4)               // 20480
#define SB_BYTES (TK * BLD * 4)               // 8704
#define STAGE_BYTES (SA_BYTES + SB_BYTES)     // 29184
#define PIPE_BYTES (STAGES * STAGE_BYTES)     // 116736
#define Z_BYTES (TM * ZLD * 4)                // 135168
#define SMEM_BYTES (Z_BYTES > PIPE_BYTES ? Z_BYTES : PIPE_BYTES)

// Scratch: pre-rounded tf32 operands
static __device__ __align__(16) float g_A[(size_t)MTOT * KTOT];   // 64 MB
static __device__ __align__(16) float g_B[(size_t)KTOT * NTOT];   // 128 MB

// ---------------------------------------------------------------- helpers
__device__ __forceinline__ uint32_t smem_u32(const void* p) {
    uint32_t a;
    asm("{ .reg .u64 t; cvta.to.shared.u64 t, %1; cvt.u32.u64 %0, t; }"
        : "=r"(a) : "l"(p));
    return a;
}

// fp32 -> tf32 round-to-nearest (kills truncation bias)
__device__ __forceinline__ uint32_t tf32r(float v) {
    uint32_t r;
    asm("cvt.rna.tf32.f32 %0, %1;" : "=r"(r) : "f"(v));
    return r;
}

__device__ __forceinline__ void cp16(uint32_t dst, const void* src) {
    asm volatile("cp.async.cg.shared.global [%0], [%1], 16;"
                 :: "r"(dst), "l"(src) : "memory");
}
__device__ __forceinline__ void cp_commit() {
    asm volatile("cp.async.commit_group;" ::: "memory");
}
template <int N>
__device__ __forceinline__ void cp_wait() {
    asm volatile("cp.async.wait_group %0;" :: "n"(N) : "memory");
}

__device__ __forceinline__ void mma8(float* d, const uint32_t* a, const uint32_t* b) {
    asm volatile(
        "mma.sync.aligned.m16n8k8.row.col.f32.tf32.tf32.f32 "
        "{%0,%1,%2,%3}, {%4,%5,%6,%7}, {%8,%9}, {%0,%1,%2,%3};"
        : "+f"(d[0]), "+f"(d[1]), "+f"(d[2]), "+f"(d[3])
        : "r"(a[0]), "r"(a[1]), "r"(a[2]), "r"(a[3]), "r"(b[0]), "r"(b[1]));
}

// ---------------------------------------------------------------- prepass
// A pack: g_A[m][0:2048]=tf32(x[m]), [2048:4096]=tf32(h[m])
__global__ void __launch_bounds__(256) pack_A_kernel(
    const float* __restrict__ x, const float* __restrict__ h)
{
    size_t qid = (size_t)blockIdx.x * 256 + threadIdx.x;  // quad id
    int m = (int)(qid >> 10);
    int col = (int)(qid & 1023) * 4;
    const float* src = (col < UDIM) ? (x + (size_t)m * UDIM + col)
                                    : (h + (size_t)m * UDIM + (col - UDIM));
    float4 v = *(const float4*)src;
    uint4 u;
    u.x = tf32r(v.x); u.y = tf32r(v.y); u.z = tf32r(v.z); u.w = tf32r(v.w);
    *(uint4*)(g_A + (size_t)m * KTOT + col) = u;
}

// W pack (gate-interleaved): g_B[k+rowoff][4u+g] = tf32(W_g[k][u])
__global__ void __launch_bounds__(256) pack_W_kernel(
    const float* __restrict__ wf, const float* __restrict__ wi,
    const float* __restrict__ wo, const float* __restrict__ wg, int rowoff)
{
    size_t id = (size_t)blockIdx.x * 256 + threadIdx.x;   // 4M elements
    int k = (int)(id >> 11);
    int u = (int)(id & 2047);
    size_t s = (size_t)k * UDIM + u;
    uint4 v;
    v.x = tf32r(wf[s]); v.y = tf32r(wi[s]); v.z = tf32r(wo[s]); v.w = tf32r(wg[s]);
    *(uint4*)(g_B + (size_t)(k + rowoff) * NTOT + 4 * u) = v;
}

// ---------------------------------------------------------------- GEMM
__device__ __forceinline__ void load_stage(char* smem, int slot, int kt,
                                           int tid, int m0, int n0)
{
    char* base = smem + slot * STAGE_BYTES;
    uint32_t sa = smem_u32(base);
    uint32_t sb = sa + SA_BYTES;
    const int k0 = kt * TK;
#pragma unroll
    for (int i = 0; i < 4; i++) {                 // A: 1024 quads
        int qid = tid + i * 256;
        int m = qid >> 2, q = qid & 3;
        cp16(sa + (uint32_t)(m * ALD + q * 4) * 4,
             g_A + (size_t)(m0 + m) * KTOT + k0 + q * 4);
    }
#pragma unroll
    for (int i = 0; i < 2; i++) {                 // B: 512 quads
        int qid = tid + i * 256;
        int k = qid >> 5, q = qid & 31;
        cp16(sb + (uint32_t)(k * BLD + q * 4) * 4,
             g_B + (size_t)(k0 + k) * NTOT + n0 + q * 4);
    }
}

__global__ void __launch_bounds__(256, 1) lstm_gemm_kernel(
    const float* __restrict__ cin,
    const float* __restrict__ bfp, const float* __restrict__ bip,
    const float* __restrict__ bop, const float* __restrict__ bgp,
    float* __restrict__ out)
{
    extern __shared__ char smem[];
    const int tid = threadIdx.x;
    const int wid = tid >> 5;
    const int lane = tid & 31;
    const int mt = blockIdx.x & 15;       // m fastest: A stays L2-resident
    const int nt = blockIdx.x >> 4;
    const int m0 = mt * TM;
    const int n0 = nt * TN;

    const int wm = (wid & 3) * 64;        // warp m offset (4 warps)
    const int wn = (wid >> 2) * 64;       // warp n offset (2 warps)
    const int gq = lane >> 2;             // group id 0..7
    const int kq = lane & 3;              // thread-in-group 0..3

    float acc[4][8][4];
#pragma unroll
    for (int mf = 0; mf < 4; mf++)
#pragma unroll
        for (int nf = 0; nf < 8; nf++)
#pragma unroll
            for (int r = 0; r < 4; r++) acc[mf][nf][r] = 0.f;

    // prologue: fill STAGES-1 stages
#pragma unroll
    for (int s = 0; s < STAGES - 1; s++) {
        load_stage(smem, s, s, tid, m0, n0);
        cp_commit();
    }

    const int KT = KTOT / TK;             // 256
    for (int kt = 0; kt < KT; kt++) {
        cp_wait<STAGES - 2>();
        __syncthreads();

        int nk = kt + STAGES - 1;
        if (nk < KT) load_stage(smem, nk & (STAGES - 1), nk, tid, m0, n0);
        cp_commit();

        const int slot = kt & (STAGES - 1);
        const uint32_t* sA = (const uint32_t*)(smem + slot * STAGE_BYTES);
        const uint32_t* sB = (const uint32_t*)(smem + slot * STAGE_BYTES + SA_BYTES);

#pragma unroll
        for (int ks = 0; ks < TK; ks += 8) {
            uint32_t a[4][4];
#pragma unroll
            for (int mf = 0; mf < 4; mf++) {
                int r0 = wm + mf * 16 + gq;
                a[mf][0] = sA[r0 * ALD + ks + kq];
                a[mf][1] = sA[(r0 + 8) * ALD + ks + kq];
                a[mf][2] = sA[r0 * ALD + ks + kq + 4];
                a[mf][3] = sA[(r0 + 8) * ALD + ks + kq + 4];
            }
            uint32_t b[8][2];
#pragma unroll
            for (int nf = 0; nf < 8; nf++) {
                int cc = wn + nf * 8 + gq;
                b[nf][0] = sB[(ks + kq) * BLD + cc];
                b[nf][1] = sB[(ks + kq + 4) * BLD + cc];
            }
#pragma unroll
            for (int mf = 0; mf < 4; mf++)
#pragma unroll
                for (int nf = 0; nf < 8; nf++)
                    mma8(acc[mf][nf], a[mf], b[nf]);
        }
    }

    cp_wait<0>();
    __syncthreads();   // pipeline done; reuse smem for z tile

    // ---- store z [256 x 128] to smem ----
    float* s_z = (float*)smem;
#pragma unroll
    for (int mf = 0; mf < 4; mf++)
#pragma unroll
        for (int nf = 0; nf < 8; nf++) {
            int row = wm + mf * 16 + gq;
            int col = wn + nf * 8 + 2 * kq;
            *(float2*)(s_z + row * ZLD + col) =
                make_float2(acc[mf][nf][0], acc[mf][nf][1]);
            *(float2*)(s_z + (row + 8) * ZLD + col) =
                make_float2(acc[mf][nf][2], acc[mf][nf][3]);
        }
    __syncthreads();

    // ---- fused LSTM gate epilogue ----
    // thread: unit-lane ul = tid&31, row block rb = tid>>5; 32 rows each
    const int ul = tid & 31;
    const int rb = tid >> 5;
    const int u = nt * 32 + ul;                 // global unit
    const float bf = __ldg(bfp + u);
    const float bi = __ldg(bip + u);
    const float bo = __ldg(bop + u);
    const float bg = __ldg(bgp + u);
    const size_t HC = (size_t)MTOT * UDIM;

#pragma unroll 4
    for (int rr = 0; rr < 32; rr++) {
        int row = rb * 32 + rr;
        float4 z = *(const float4*)(s_z + row * ZLD + 4 * ul);
        size_t g = (size_t)(m0 + row) * UDIM + u;
        float zf = z.x + bf, zi = z.y + bi, zo = z.z + bo, zg = z.w + bg;
        float fg = 1.f / (1.f + expf(-zf));
        float ig = 1.f / (1.f + expf(-zi));
        float og = 1.f / (1.f + expf(-zo));
        float gg = tanhf(zg);
        float cn = fg * __ldg(cin + g) + ig * gg;
        float hn = og * tanhf(cn);
        out[g] = hn;          // h_new
        out[HC + g] = cn;     // c_new
    }
}

// ---------------------------------------------------------------- launch
extern "C" void kernel_launch(void* const* d_in, const int* in_sizes, int n_in,
                              void* d_out, int out_size) {
    (void)in_sizes; (void)n_in; (void)out_size;
    const float* x   = (const float*)d_in[0];
    const float* h   = (const float*)d_in[1];
    const float* c   = (const float*)d_in[2];
    const float* Wxf = (const float*)d_in[3];
    const float* Wxi = (const float*)d_in[4];
    const float* Wxo = (const float*)d_in[5];
    const float* Wxg = (const float*)d_in[6];
    const float* bf  = (const float*)d_in[7];
    const float* bi  = (const float*)d_in[8];
    const float* bo  = (const float*)d_in[9];
    const float* bg  = (const float*)d_in[10];
    const float* Whf = (const float*)d_in[11];
    const float* Whi = (const float*)d_in[12];
    const float* Who = (const float*)d_in[13];
    const float* Whg = (const float*)d_in[14];
    float* out = (float*)d_out;

    static int smem_set = 0;
    if (!smem_set) {
        cudaFuncSetAttribute(lstm_gemm_kernel,
                             cudaFuncAttributeMaxDynamicSharedMemorySize,
                             SMEM_BYTES);
        smem_set = 1;
    }

    pack_A_kernel<<<(MTOT * (KTOT / 4)) / 256, 256>>>(x, h);
    pack_W_kernel<<<(UDIM * UDIM) / 256, 256>>>(Wxf, Wxi, Wxo, Wxg, 0);
    pack_W_kernel<<<(UDIM * UDIM) / 256, 256>>>(Whf, Whi, Who, Whg, UDIM);
    lstm_gemm_kernel<<<(MTOT / TM) * (NTOT / TN), 256, SMEM_BYTES>>>(
        c, bf, bi, bo, bg, out);
}

// round 3
// speedup vs baseline: 1.1436x; 1.1436x over previous
#include <cuda_runtime.h>
#include <cstdint>

// ============================================================================
// LSTM cell, base sm_103 ISA. tf32 mma.sync m16n8k8 GEMM, cp.async 4-stage,
// fragment-packed operands (LDS.128/LDS.64 fragment loads), fused gate epilogue.
//
// z[4096, 8192] = A[4096, 4096] @ B[4096, 8192]
//   A = [x | h], B[k][4u+g] = W{x,h}{f,i,o,g}[k][u]  (gate-interleaved)
// ============================================================================

#define MTOT 4096
#define KTOT 4096
#define NTOT 8192
#define UDIM 2048

#define TM 256
#define TN 128
#define TK 16          // 2 k8 sub-steps per stage
#define STAGES 4
#define NTHREADS 512

#define K8TOT 512              // KTOT/8
#define MBTOT 256              // MTOT/16
#define NBTOT 1024             // NTOT/8

#define SA_STAGE 16384         // 2 k8 * 16 mb * 512 B
#define SB_STAGE 8192          // 2 k8 * 16 nb * 256 B
#define STAGE_BYTES (SA_STAGE + SB_STAGE)      // 24576
#define PIPE_BYTES (STAGES * STAGE_BYTES)      // 98304
#define ZLD 132
#define Z_BYTES (TM * ZLD * 4)                 // 135168
#define SMEM_BYTES (Z_BYTES > PIPE_BYTES ? Z_BYTES : PIPE_BYTES)

// Fragment-packed tf32 operands.
// g_Ap[k8][mb][lane][4] : lane=(gq<<2)|kq holds A[mb*16+gq+{0,8}][k8*8+kq+{0,4}]
// g_Bp[k8][nb][lane][2] : lane=(nq<<2)|kq holds B[k8*8+kq+{0,4}][nb*8+nq]
static __device__ __align__(16) float g_Ap[(size_t)MTOT * KTOT];   // 64 MB
static __device__ __align__(16) float g_Bp[(size_t)KTOT * NTOT];   // 128 MB

// ---------------------------------------------------------------- helpers
__device__ __forceinline__ uint32_t smem_u32(const void* p) {
    uint32_t a;
    asm("{ .reg .u64 t; cvta.to.shared.u64 t, %1; cvt.u32.u64 %0, t; }"
        : "=r"(a) : "l"(p));
    return a;
}

__device__ __forceinline__ uint32_t tf32r(float v) {   // round-to-nearest tf32
    uint32_t r;
    asm("cvt.rna.tf32.f32 %0, %1;" : "=r"(r) : "f"(v));
    return r;
}

__device__ __forceinline__ void cp16(uint32_t dst, const void* src) {
    asm volatile("cp.async.cg.shared.global [%0], [%1], 16;"
                 :: "r"(dst), "l"(src) : "memory");
}
__device__ __forceinline__ void cp_commit() {
    asm volatile("cp.async.commit_group;" ::: "memory");
}
template <int N>
__device__ __forceinline__ void cp_wait() {
    asm volatile("cp.async.wait_group %0;" :: "n"(N) : "memory");
}

__device__ __forceinline__ void mma8(float* d, const uint32_t* a, const uint32_t* b) {
    asm volatile(
        "mma.sync.aligned.m16n8k8.row.col.f32.tf32.tf32.f32 "
        "{%0,%1,%2,%3}, {%4,%5,%6,%7}, {%8,%9}, {%0,%1,%2,%3};"
        : "+f"(d[0]), "+f"(d[1]), "+f"(d[2]), "+f"(d[3])
        : "r"(a[0]), "r"(a[1]), "r"(a[2]), "r"(a[3]), "r"(b[0]), "r"(b[1]));
}

// ---------------------------------------------------------------- prepasses
// A pack: thread t = (k8, mb, lane); writes g_Ap + t*4 (uint4).
__global__ void __launch_bounds__(256) pack_A_kernel(
    const float* __restrict__ x, const float* __restrict__ h)
{
    uint32_t t = blockIdx.x * 256 + threadIdx.x;     // 4,194,304 threads
    int lane = t & 31;
    int mb = (t >> 5) & 255;
    int k8 = t >> 13;
    int kq = lane & 3, gq = lane >> 2;
    int m = mb * 16 + gq;
    int k = k8 * 8 + kq;
    const float* src = (k < UDIM) ? (x + k) : (h + (k - UDIM));
    uint4 u;
    u.x = tf32r(src[(size_t)m * UDIM]);
    u.y = tf32r(src[(size_t)(m + 8) * UDIM]);
    u.z = tf32r(src[(size_t)m * UDIM + 4]);
    u.w = tf32r(src[(size_t)(m + 8) * UDIM + 4]);
    *(uint4*)(g_Ap + (size_t)t * 4) = u;
}

// B pack: thread t = (k8, nb, lane); writes g_Bp + t*2 (float2).
__global__ void __launch_bounds__(256) pack_W_kernel(
    const float* __restrict__ wxf, const float* __restrict__ wxi,
    const float* __restrict__ wxo, const float* __restrict__ wxg,
    const float* __restrict__ whf, const float* __restrict__ whi,
    const float* __restrict__ who, const float* __restrict__ whg)
{
    uint32_t t = blockIdx.x * 256 + threadIdx.x;     // 16,777,216 threads
    int lane = t & 31;
    int nb = (t >> 5) & 1023;
    int k8 = t >> 15;
    int kq = lane & 3, nq = lane >> 2;
    int n = nb * 8 + nq;
    int u = n >> 2, g = n & 3;
    int k = k8 * 8 + kq;                 // 0..4095
    const float* W;
    if (k < UDIM) {
        W = (g == 0) ? wxf : (g == 1) ? wxi : (g == 2) ? wxo : wxg;
    } else {
        W = (g == 0) ? whf : (g == 1) ? whi : (g == 2) ? who : whg;
        k -= UDIM;
    }
    float2 v;
    v.x = __uint_as_float(tf32r(W[(size_t)k * UDIM + u]));
    v.y = __uint_as_float(tf32r(W[(size_t)(k + 4) * UDIM + u]));
    *(float2*)(g_Bp + (size_t)t * 2) = v;
}

// ---------------------------------------------------------------- GEMM
__device__ __forceinline__ void load_stage(uint32_t sbase, int slot, int kt,
                                           int tid, int mb0, int nb0)
{
    uint32_t sa = sbase + slot * STAGE_BYTES;
    uint32_t sb = sa + SA_STAGE;
    const int k8 = kt * 2;
    const float* a0 = g_Ap + (size_t)k8 * (MBTOT * 128) + mb0 * 128;
    const float* b0 = g_Bp + (size_t)k8 * (NBTOT * 64) + nb0 * 64;
    // A: 2 x 8KB linear
    cp16(sa + tid * 16, a0 + tid * 4);
    cp16(sa + 8192 + tid * 16, a0 + MBTOT * 128 + tid * 4);
    // B: 2 x 4KB linear
    if (tid < 256) cp16(sb + tid * 16, b0 + tid * 4);
    else           cp16(sb + 4096 + (tid - 256) * 16, b0 + NBTOT * 64 + (tid - 256) * 4);
}

__global__ void __launch_bounds__(NTHREADS, 1) lstm_gemm_kernel(
    const float* __restrict__ cin,
    const float* __restrict__ bfp, const float* __restrict__ bip,
    const float* __restrict__ bop, const float* __restrict__ bgp,
    float* __restrict__ out)
{
    extern __shared__ char smem[];
    const uint32_t sbase = smem_u32(smem);
    const int tid = threadIdx.x;
    const int wid = tid >> 5;
    const int lane = tid & 31;
    const int mt = blockIdx.x & 15;          // m fastest: A stays L2-resident
    const int nt = blockIdx.x >> 4;
    const int mb0 = mt * 16;                 // 16 mb blocks per CTA
    const int nb0 = nt * 16;                 // 16 nb blocks per CTA

    const int wm = (wid & 3) * 64;           // warp tile 64 x 32
    const int wn = (wid >> 2) * 32;
    const uint32_t a_off = (uint32_t)((wid & 3) * 4) * 512 + lane * 16;
    const uint32_t b_off = (uint32_t)((wid >> 2) * 4) * 256 + lane * 8;

    float acc[4][4][4];
#pragma unroll
    for (int mf = 0; mf < 4; mf++)
#pragma unroll
        for (int nf = 0; nf < 4; nf++)
#pragma unroll
            for (int r = 0; r < 4; r++) acc[mf][nf][r] = 0.f;

#pragma unroll
    for (int s = 0; s < STAGES - 1; s++) {
        load_stage(sbase, s, s, tid, mb0, nb0);
        cp_commit();
    }

    const int KT = KTOT / TK;                // 256
    for (int kt = 0; kt < KT; kt++) {
        cp_wait<STAGES - 2>();
        __syncthreads();

        int nk = kt + STAGES - 1;
        if (nk < KT) load_stage(sbase, nk & (STAGES - 1), nk, tid, mb0, nb0);
        cp_commit();

        const uint32_t sa = sbase + (kt & (STAGES - 1)) * STAGE_BYTES;
        const uint32_t sb = sa + SA_STAGE;

#pragma unroll
        for (int ks = 0; ks < 2; ks++) {
            uint32_t a[4][4];
#pragma unroll
            for (int mf = 0; mf < 4; mf++) {
                uint32_t addr = sa + ks * 8192 + mf * 512 + a_off;
                asm volatile("ld.shared.v4.b32 {%0,%1,%2,%3}, [%4];"
                             : "=r"(a[mf][0]), "=r"(a[mf][1]),
                               "=r"(a[mf][2]), "=r"(a[mf][3])
                             : "r"(addr));
            }
            uint32_t b[4][2];
#pragma unroll
            for (int nf = 0; nf < 4; nf++) {
                uint32_t addr = sb + ks * 4096 + nf * 256 + b_off;
                asm volatile("ld.shared.v2.b32 {%0,%1}, [%2];"
                             : "=r"(b[nf][0]), "=r"(b[nf][1])
                             : "r"(addr));
            }
#pragma unroll
            for (int mf = 0; mf < 4; mf++)
#pragma unroll
                for (int nf = 0; nf < 4; nf++)
                    mma8(acc[mf][nf], a[mf], b[nf]);
        }
    }

    cp_wait<0>();
    __syncthreads();     // pipeline done; reuse smem for z tile

    // ---- z [256 x 128] to smem ----
    float* s_z = (float*)smem;
    const int gq = lane >> 2, kq = lane & 3;
#pragma unroll
    for (int mf = 0; mf < 4; mf++)
#pragma unroll
        for (int nf = 0; nf < 4; nf++) {
            int row = wm + mf * 16 + gq;
            int col = wn + nf * 8 + 2 * kq;
            *(float2*)(s_z + row * ZLD + col) =
                make_float2(acc[mf][nf][0], acc[mf][nf][1]);
            *(float2*)(s_z + (row + 8) * ZLD + col) =
                make_float2(acc[mf][nf][2], acc[mf][nf][3]);
        }
    __syncthreads();

    // ---- fused LSTM gate epilogue ----
    const int ul = tid & 31;                 // unit lane within 32-unit tile
    const int rb = tid >> 5;                 // 16 row blocks of 16 rows
    const int u = nt * 32 + ul;
    const int m0 = mt * TM;
    const float bf = __ldg(bfp + u);
    const float bi = __ldg(bip + u);
    const float bo = __ldg(bop + u);
    const float bg = __ldg(bgp + u);
    const size_t HC = (size_t)MTOT * UDIM;

#pragma unroll 4
    for (int rr = 0; rr < 16; rr++) {
        int row = rb * 16 + rr;
        float4 z = *(const float4*)(s_z + row * ZLD + 4 * ul);
        size_t g = (size_t)(m0 + row) * UDIM + u;
        float zf = z.x + bf, zi = z.y + bi, zo = z.z + bo, zg = z.w + bg;
        float fg = 1.f / (1.f + expf(-zf));
        float ig = 1.f / (1.f + expf(-zi));
        float og = 1.f / (1.f + expf(-zo));
        float gg = tanhf(zg);
        float cn = fg * __ldg(cin + g) + ig * gg;
        float hn = og * tanhf(cn);
        out[g] = hn;          // h_new
        out[HC + g] = cn;     // c_new
    }
}

// ---------------------------------------------------------------- launch
extern "C" void kernel_launch(void* const* d_in, const int* in_sizes, int n_in,
                              void* d_out, int out_size) {
    (void)in_sizes; (void)n_in; (void)out_size;
    const float* x   = (const float*)d_in[0];
    const float* h   = (const float*)d_in[1];
    const float* c   = (const float*)d_in[2];
    const float* Wxf = (const float*)d_in[3];
    const float* Wxi = (const float*)d_in[4];
    const float* Wxo = (const float*)d_in[5];
    const float* Wxg = (const float*)d_in[6];
    const float* bf  = (const float*)d_in[7];
    const float* bi  = (const float*)d_in[8];
    const float* bo  = (const float*)d_in[9];
    const float* bg  = (const float*)d_in[10];
    const float* Whf = (const float*)d_in[11];
    const float* Whi = (const float*)d_in[12];
    const float* Who = (const float*)d_in[13];
    const float* Whg = (const float*)d_in[14];
    float* out = (float*)d_out;

    static int smem_set = 0;
    if (!smem_set) {
        cudaFuncSetAttribute(lstm_gemm_kernel,
                             cudaFuncAttributeMaxDynamicSharedMemorySize,
                             SMEM_BYTES);
        smem_set = 1;
    }

    pack_A_kernel<<<(MTOT / 16) * (KTOT / 8) * 32 / 256, 256>>>(x, h);
    pack_W_kernel<<<(KTOT / 8) * (NTOT / 8) * 32 / 256, 256>>>(
        Wxf, Wxi, Wxo, Wxg, Whf, Whi, Who, Whg);
    lstm_gemm_kernel<<<(MTOT / TM) * (NTOT / TN), NTHREADS, SMEM_BYTES>>>(
        c, bf, bi, bo, bg, out);
}